// round 3
// baseline (speedup 1.0000x reference)
#include <cuda_runtime.h>
#include <cuda_bf16.h>

#define N_NODES 100000
#define N_GRAPHS 512
#define HID 16
#define LABELS 10
#define VOCAB 128

// ---------------- scratch (device globals; no allocation allowed) ----------
__device__ float  g_dinv[N_NODES];          // deg -> rsqrt(deg), in place
__device__ float4 g_out1[N_NODES * 4];      // layer-1 accumulator (16 f32/node)
__device__ float4 g_hw2 [N_NODES * 4];      // relu(out1+b1) @ W2
__device__ float4 g_out2[N_NODES * 4];      // layer-2 accumulator
__device__ float4 g_EW  [VOCAB * 4];        // emb @ W1   (128 x 16)
__device__ float  g_sums[N_GRAPHS * HID];
__device__ float  g_cnt [N_GRAPHS];

// 16-byte vector reduction into global (sm_90+): 4x fewer L2 atomic ops
__device__ __forceinline__ void red4(float4* p, float a, float b, float c, float d) {
    asm volatile("red.global.add.v4.f32 [%0], {%1,%2,%3,%4};"
                 :: "l"(p), "f"(a), "f"(b), "f"(c), "f"(d) : "memory");
}

// ---------------- kernels ---------------------------------------------------

// dinv := 1 (self loop), zero pooling scratch
__global__ __launch_bounds__(256) void k_init() {
    int i = blockIdx.x * blockDim.x + threadIdx.x;
    if (i < N_NODES) g_dinv[i] = 1.0f;
    if (i < N_GRAPHS * HID) g_sums[i] = 0.0f;
    if (i < N_GRAPHS) g_cnt[i] = 0.0f;
}

// deg[dst] += 1 over real edges
__global__ __launch_bounds__(256) void k_deg(const int* __restrict__ dst, int E) {
    int e = blockIdx.x * blockDim.x + threadIdx.x;
    if (e < E) atomicAdd(&g_dinv[dst[e]], 1.0f);
}

__global__ __launch_bounds__(256) void k_rsqrt() {
    int i = blockIdx.x * blockDim.x + threadIdx.x;
    if (i < N_NODES) g_dinv[i] = rsqrtf(g_dinv[i]);   // deg >= 1 always (self loop)
}

// EW = emb @ W1   (128x16 @ 16x16), one block of 128 threads
__global__ void k_ew(const float* __restrict__ emb, const float* __restrict__ W1) {
    __shared__ float sW[HID * HID];
    int t = threadIdx.x;
    sW[t] = W1[t];
    sW[t + 128] = W1[t + 128];
    __syncthreads();
    float h[HID];
#pragma unroll
    for (int k = 0; k < HID; k++) h[k] = emb[t * HID + k];
    float o[HID];
#pragma unroll
    for (int j = 0; j < HID; j++) {
        float s = 0.0f;
#pragma unroll
        for (int k = 0; k < HID; k++) s = fmaf(h[k], sW[k * HID + j], s);
        o[j] = s;
    }
#pragma unroll
    for (int q = 0; q < 4; q++)
        g_EW[t * 4 + q] = make_float4(o[4 * q], o[4 * q + 1], o[4 * q + 2], o[4 * q + 3]);
}

// out1[i] = EW[x[i]] * dinv[i]^2   (self-loop term written directly, no atomics)
__global__ __launch_bounds__(256) void k_self1(const int* __restrict__ x) {
    int i = blockIdx.x * blockDim.x + threadIdx.x;
    if (i >= N_NODES) return;
    float w = g_dinv[i]; w *= w;
    const float4* r = &g_EW[x[i] * 4];
#pragma unroll
    for (int q = 0; q < 4; q++) {
        float4 v = r[q];
        g_out1[i * 4 + q] = make_float4(v.x * w, v.y * w, v.z * w, v.w * w);
    }
}

// out1[dst] += EW[x[src]] * dinv[src]*dinv[dst]
__global__ __launch_bounds__(256) void k_edge1(const int* __restrict__ src,
                                               const int* __restrict__ dst,
                                               const int* __restrict__ x, int E) {
    int e = blockIdx.x * blockDim.x + threadIdx.x;
    if (e >= E) return;
    int s = src[e], d = dst[e];
    float w = __ldg(&g_dinv[s]) * __ldg(&g_dinv[d]);
    const float4* r = &g_EW[__ldg(&x[s]) * 4];
    float4* o = &g_out1[d * 4];
#pragma unroll
    for (int q = 0; q < 4; q++) {
        float4 v = __ldg(&r[q]);
        red4(o + q, v.x * w, v.y * w, v.z * w, v.w * w);
    }
}

// hw2[i] = relu(out1[i]+b1) @ W2 ;  out2[i] = hw2[i] * dinv[i]^2
__global__ __launch_bounds__(256) void k_l2(const float* __restrict__ b1,
                                            const float* __restrict__ W2) {
    __shared__ float sW[HID * HID];
    __shared__ float sb[HID];
    if (threadIdx.x < HID * HID) sW[threadIdx.x] = W2[threadIdx.x];
    if (threadIdx.x < HID) sb[threadIdx.x] = b1[threadIdx.x];
    __syncthreads();
    int i = blockIdx.x * blockDim.x + threadIdx.x;
    if (i >= N_NODES) return;
    float h[HID];
#pragma unroll
    for (int q = 0; q < 4; q++) {
        float4 v = g_out1[i * 4 + q];
        h[4 * q + 0] = fmaxf(v.x + sb[4 * q + 0], 0.0f);
        h[4 * q + 1] = fmaxf(v.y + sb[4 * q + 1], 0.0f);
        h[4 * q + 2] = fmaxf(v.z + sb[4 * q + 2], 0.0f);
        h[4 * q + 3] = fmaxf(v.w + sb[4 * q + 3], 0.0f);
    }
    float o[HID];
#pragma unroll
    for (int j = 0; j < HID; j++) o[j] = 0.0f;
#pragma unroll
    for (int k = 0; k < HID; k++)
#pragma unroll
        for (int j = 0; j < HID; j++) o[j] = fmaf(h[k], sW[k * HID + j], o[j]);
    float w = g_dinv[i]; w *= w;
#pragma unroll
    for (int q = 0; q < 4; q++) {
        g_hw2 [i * 4 + q] = make_float4(o[4*q], o[4*q+1], o[4*q+2], o[4*q+3]);
        g_out2[i * 4 + q] = make_float4(o[4*q]*w, o[4*q+1]*w, o[4*q+2]*w, o[4*q+3]*w);
    }
}

// out2[dst] += hw2[src] * dinv[src]*dinv[dst]
__global__ __launch_bounds__(256) void k_edge2(const int* __restrict__ src,
                                               const int* __restrict__ dst, int E) {
    int e = blockIdx.x * blockDim.x + threadIdx.x;
    if (e >= E) return;
    int s = src[e], d = dst[e];
    float w = __ldg(&g_dinv[s]) * __ldg(&g_dinv[d]);
    const float4* r = &g_hw2[s * 4];
    float4* o = &g_out2[d * 4];
#pragma unroll
    for (int q = 0; q < 4; q++) {
        float4 v = __ldg(&r[q]);
        red4(o + q, v.x * w, v.y * w, v.z * w, v.w * w);
    }
}

// h2 = relu(out2+b2); sums[batch[i]] += h2 ; cnt[batch[i]] += 1
// batch is sorted -> most warps are graph-uniform: shuffle-reduce, 1 red per warp.
__global__ __launch_bounds__(256) void k_pool(const int* __restrict__ batch,
                                              const float* __restrict__ b2) {
    __shared__ float sb[HID];
    if (threadIdx.x < HID) sb[threadIdx.x] = b2[threadIdx.x];
    __syncthreads();
    int i = blockIdx.x * blockDim.x + threadIdx.x;
    int lane = threadIdx.x & 31;
    float h[HID];
    int b = -1;
    if (i < N_NODES) {
        b = batch[i];
#pragma unroll
        for (int q = 0; q < 4; q++) {
            float4 v = g_out2[i * 4 + q];
            h[4*q+0] = fmaxf(v.x + sb[4*q+0], 0.0f);
            h[4*q+1] = fmaxf(v.y + sb[4*q+1], 0.0f);
            h[4*q+2] = fmaxf(v.z + sb[4*q+2], 0.0f);
            h[4*q+3] = fmaxf(v.w + sb[4*q+3], 0.0f);
        }
    } else {
#pragma unroll
        for (int k = 0; k < HID; k++) h[k] = 0.0f;
    }
    int b0 = __shfl_sync(0xffffffffu, b, 0);
    bool uniform = __all_sync(0xffffffffu, b == b0);
    if (uniform && b0 >= 0) {
        // whole warp same graph (and all valid): tree-reduce then single red
#pragma unroll
        for (int k = 0; k < HID; k++) {
#pragma unroll
            for (int off = 16; off > 0; off >>= 1)
                h[k] += __shfl_down_sync(0xffffffffu, h[k], off);
        }
        if (lane == 0) {
            float4* p = (float4*)&g_sums[b0 * HID];
#pragma unroll
            for (int q = 0; q < 4; q++)
                red4(p + q, h[4*q], h[4*q+1], h[4*q+2], h[4*q+3]);
            atomicAdd(&g_cnt[b0], 32.0f);
        }
    } else if (b >= 0) {
        float4* p = (float4*)&g_sums[b * HID];
#pragma unroll
        for (int q = 0; q < 4; q++)
            red4(p + q, h[4*q], h[4*q+1], h[4*q+2], h[4*q+3]);
        atomicAdd(&g_cnt[b], 1.0f);
    }
}

// out[g] = (sums[g]/max(cnt,1)) @ Wc + bc    (512 x 10)
__global__ __launch_bounds__(256) void k_final(const float* __restrict__ Wc,
                                               const float* __restrict__ bc,
                                               float* __restrict__ out) {
    int g = blockIdx.x * blockDim.x + threadIdx.x;
    if (g >= N_GRAPHS) return;
    float inv = 1.0f / fmaxf(g_cnt[g], 1.0f);
    float p[HID];
#pragma unroll
    for (int k = 0; k < HID; k++) p[k] = g_sums[g * HID + k] * inv;
#pragma unroll
    for (int j = 0; j < LABELS; j++) {
        float s = __ldg(&bc[j]);
#pragma unroll
        for (int k = 0; k < HID; k++) s = fmaf(p[k], __ldg(&Wc[k * LABELS + j]), s);
        out[g * LABELS + j] = s;
    }
}

// ---------------- launch -----------------------------------------------------
extern "C" void kernel_launch(void* const* d_in, const int* in_sizes, int n_in,
                              void* d_out, int out_size) {
    const int*   x    = (const int*)  d_in[0];
    const int*   ei   = (const int*)  d_in[1];
    const int*   batch= (const int*)  d_in[2];
    const float* emb  = (const float*)d_in[3];
    const float* W1   = (const float*)d_in[4];
    const float* b1   = (const float*)d_in[5];
    const float* W2   = (const float*)d_in[6];
    const float* b2   = (const float*)d_in[7];
    const float* Wc   = (const float*)d_in[8];
    const float* bc   = (const float*)d_in[9];
    float* out = (float*)d_out;

    int E = in_sizes[1] / 2;
    const int* src = ei;
    const int* dst = ei + E;

    int gn = (N_NODES + 255) / 256;
    int ge = (E + 255) / 256;

    k_init  <<<gn, 256>>>();
    k_deg   <<<ge, 256>>>(dst, E);
    k_rsqrt <<<gn, 256>>>();
    k_ew    <<<1, 128>>>(emb, W1);
    k_self1 <<<gn, 256>>>(x);
    k_edge1 <<<ge, 256>>>(src, dst, x, E);
    k_l2    <<<gn, 256>>>(b1, W2);
    k_edge2 <<<ge, 256>>>(src, dst, E);
    k_pool  <<<gn, 256>>>(batch, b2);
    k_final <<<(N_GRAPHS + 255) / 256, 256>>>(Wc, bc, out);
}

// round 6
// speedup vs baseline: 1.7939x; 1.7939x over previous
#include <cuda_runtime.h>
#include <cuda_bf16.h>

#define N_NODES  100000
#define N_EDGES  3200000
#define N_GRAPHS 512
#define HID      16
#define LABELS   10
#define VOCAB    128

#define SCAN_BLK 1024
#define SCAN_NB  ((N_NODES + SCAN_BLK - 1) / SCAN_BLK)   // 98

// ---------------- scratch (device globals; no allocation allowed) ----------
__device__ int    g_deg   [N_NODES];        // real in-degree
__device__ int    g_off   [N_NODES];        // CSR exclusive offsets
__device__ int    g_cursor[N_NODES];        // scatter cursors
__device__ int    g_bsum  [SCAN_NB];        // per-block scan totals
__device__ int    g_bbase [SCAN_NB];        // scanned block bases
__device__ int    g_csr   [N_EDGES];        // src sorted by dst
__device__ float  g_dinv  [N_NODES];
__device__ float4 g_a1    [N_NODES * 4];    // EW[x[i]] * dinv[i]
__device__ float4 g_h1    [N_NODES * 4];    // relu(layer1)
__device__ float4 g_a2    [N_NODES * 4];    // (h1 @ W2) * dinv[i]
__device__ float4 g_h2    [N_NODES * 4];    // relu(layer2)
__device__ float4 g_EW    [VOCAB * 4];      // emb @ W1   (128 x 16)
__device__ float  g_sums  [N_GRAPHS * HID];
__device__ float  g_cnt   [N_GRAPHS];

__device__ __forceinline__ void red4(float4* p, float a, float b, float c, float d) {
    asm volatile("red.global.add.v4.f32 [%0], {%1,%2,%3,%4};"
                 :: "l"(p), "f"(a), "f"(b), "f"(c), "f"(d) : "memory");
}

// ---------------- build: degree, scan, scatter ------------------------------

__global__ __launch_bounds__(256) void k_init() {
    int i = blockIdx.x * blockDim.x + threadIdx.x;
    if (i < N_NODES) g_deg[i] = 0;
    if (i < N_GRAPHS * HID) g_sums[i] = 0.0f;
    if (i < N_GRAPHS) g_cnt[i] = 0.0f;
}

__global__ __launch_bounds__(256) void k_deg(const int* __restrict__ dst, int E) {
    int e = blockIdx.x * blockDim.x + threadIdx.x;
    if (e < E) atomicAdd(&g_deg[dst[e]], 1);
}

// per-block exclusive scan (1024 elems/block)
__global__ __launch_bounds__(SCAN_BLK) void k_scan1() {
    __shared__ int s[SCAN_BLK];
    int gid = blockIdx.x * SCAN_BLK + threadIdx.x;
    int v = (gid < N_NODES) ? g_deg[gid] : 0;
    s[threadIdx.x] = v;
    __syncthreads();
#pragma unroll
    for (int off = 1; off < SCAN_BLK; off <<= 1) {
        int t = (threadIdx.x >= off) ? s[threadIdx.x - off] : 0;
        __syncthreads();
        s[threadIdx.x] += t;
        __syncthreads();
    }
    if (gid < N_NODES) g_off[gid] = s[threadIdx.x] - v;   // exclusive within block
    if (threadIdx.x == SCAN_BLK - 1) g_bsum[blockIdx.x] = s[threadIdx.x];
}

// scan the <=128 block totals with one block
__global__ __launch_bounds__(128) void k_scan2() {
    __shared__ int s[128];
    int v = (threadIdx.x < SCAN_NB) ? g_bsum[threadIdx.x] : 0;
    s[threadIdx.x] = v;
    __syncthreads();
#pragma unroll
    for (int off = 1; off < 128; off <<= 1) {
        int t = (threadIdx.x >= off) ? s[threadIdx.x - off] : 0;
        __syncthreads();
        s[threadIdx.x] += t;
        __syncthreads();
    }
    if (threadIdx.x < SCAN_NB) g_bbase[threadIdx.x] = s[threadIdx.x] - v;  // exclusive
}

// finalize offsets, cursors, dinv
__global__ __launch_bounds__(256) void k_scan3() {
    int i = blockIdx.x * blockDim.x + threadIdx.x;
    if (i >= N_NODES) return;
    int o = g_off[i] + g_bbase[i >> 10];
    g_off[i] = o;
    g_cursor[i] = o;
    g_dinv[i] = rsqrtf((float)g_deg[i] + 1.0f);   // +1 self loop
}

__global__ __launch_bounds__(256) void k_scatter(const int* __restrict__ src,
                                                 const int* __restrict__ dst, int E) {
    int e = blockIdx.x * blockDim.x + threadIdx.x;
    if (e >= E) return;
    int d = dst[e];
    int pos = atomicAdd(&g_cursor[d], 1);
    g_csr[pos] = src[e];
}

// ---------------- dense prep -------------------------------------------------

// EW = emb @ W1   (128x16 @ 16x16), one block of 128 threads
__global__ void k_ew(const float* __restrict__ emb, const float* __restrict__ W1) {
    __shared__ float sW[HID * HID];
    int t = threadIdx.x;
    sW[t] = W1[t];
    sW[t + 128] = W1[t + 128];
    __syncthreads();
    float h[HID];
#pragma unroll
    for (int k = 0; k < HID; k++) h[k] = emb[t * HID + k];
#pragma unroll
    for (int q = 0; q < 4; q++) {
        float o[4];
#pragma unroll
        for (int jj = 0; jj < 4; jj++) {
            float s = 0.0f;
#pragma unroll
            for (int k = 0; k < HID; k++) s = fmaf(h[k], sW[k * HID + 4 * q + jj], s);
            o[jj] = s;
        }
        g_EW[t * 4 + q] = make_float4(o[0], o[1], o[2], o[3]);
    }
}

// a1[i] = EW[x[i]] * dinv[i]
__global__ __launch_bounds__(256) void k_a1(const int* __restrict__ x) {
    int i = blockIdx.x * blockDim.x + threadIdx.x;
    if (i >= N_NODES) return;
    float di = g_dinv[i];
    const float4* r = &g_EW[x[i] * 4];
#pragma unroll
    for (int q = 0; q < 4; q++) {
        float4 v = r[q];
        g_a1[i * 4 + q] = make_float4(v.x * di, v.y * di, v.z * di, v.w * di);
    }
}

// ---------------- CSR gather (warp per node, 4 lanes per edge) --------------
// out[i] = relu( dinv[i] * (sum_{s->i} val[s] + val[i]) + bias )
__device__ __forceinline__ void gather_node(const float4* __restrict__ val,
                                            const float* __restrict__ bias,
                                            float4* __restrict__ outp) {
    int warp = (blockIdx.x * blockDim.x + threadIdx.x) >> 5;
    if (warp >= N_NODES) return;
    int lane = threadIdx.x & 31;
    int eq = lane >> 2;       // 0..7  edge slot within 8-wide group
    int fj = lane & 3;        // 0..3  float4 block of the feature row

    int off = __ldg(&g_off[warp]);
    int deg = __ldg(&g_deg[warp]);

    float4 acc = make_float4(0.f, 0.f, 0.f, 0.f);
    for (int base = 0; base < deg; base += 8) {
        int e = base + eq;
        if (e < deg) {
            int s = __ldg(&g_csr[off + e]);
            float4 v = __ldg(&val[s * 4 + fj]);   // 4 lanes -> same 64B row: 1 line
            acc.x += v.x; acc.y += v.y; acc.z += v.z; acc.w += v.w;
        }
    }
    // reduce across the 8 edge groups (stride 16, 8, 4 keeps fj fixed)
#pragma unroll
    for (int offv = 16; offv >= 4; offv >>= 1) {
        acc.x += __shfl_down_sync(0xffffffffu, acc.x, offv);
        acc.y += __shfl_down_sync(0xffffffffu, acc.y, offv);
        acc.z += __shfl_down_sync(0xffffffffu, acc.z, offv);
        acc.w += __shfl_down_sync(0xffffffffu, acc.w, offv);
    }
    if (lane < 4) {
        float4 self = __ldg(&val[warp * 4 + lane]);
        float di = __ldg(&g_dinv[warp]);
        float4 b = __ldg((const float4*)bias + lane);
        float4 o;
        o.x = fmaxf((acc.x + self.x) * di + b.x, 0.0f);
        o.y = fmaxf((acc.y + self.y) * di + b.y, 0.0f);
        o.z = fmaxf((acc.z + self.z) * di + b.z, 0.0f);
        o.w = fmaxf((acc.w + self.w) * di + b.w, 0.0f);
        outp[warp * 4 + lane] = o;
    }
}

__global__ __launch_bounds__(256) void k_gather1(const float* __restrict__ b1) {
    gather_node(g_a1, b1, g_h1);
}
__global__ __launch_bounds__(256) void k_gather2(const float* __restrict__ b2) {
    gather_node(g_a2, b2, g_h2);
}

// a2[i] = (h1[i] @ W2) * dinv[i]
__global__ __launch_bounds__(256) void k_l2(const float* __restrict__ W2) {
    __shared__ float sW[HID * HID];
    if (threadIdx.x < HID * HID) sW[threadIdx.x] = W2[threadIdx.x];
    __syncthreads();
    int i = blockIdx.x * blockDim.x + threadIdx.x;
    if (i >= N_NODES) return;
    float h[HID];
#pragma unroll
    for (int q = 0; q < 4; q++) {
        float4 v = g_h1[i * 4 + q];
        h[4 * q + 0] = v.x; h[4 * q + 1] = v.y; h[4 * q + 2] = v.z; h[4 * q + 3] = v.w;
    }
    float o[HID];
#pragma unroll
    for (int j = 0; j < HID; j++) o[j] = 0.0f;
#pragma unroll
    for (int k = 0; k < HID; k++)
#pragma unroll
        for (int j = 0; j < HID; j++) o[j] = fmaf(h[k], sW[k * HID + j], o[j]);
    float di = g_dinv[i];
#pragma unroll
    for (int q = 0; q < 4; q++)
        g_a2[i * 4 + q] = make_float4(o[4*q]*di, o[4*q+1]*di, o[4*q+2]*di, o[4*q+3]*di);
}

// pooling: batch sorted -> warp-uniform segments reduce via shuffles
__global__ __launch_bounds__(256) void k_pool(const int* __restrict__ batch) {
    int i = blockIdx.x * blockDim.x + threadIdx.x;
    int lane = threadIdx.x & 31;
    float h[HID];
    int b = -1;
    if (i < N_NODES) {
        b = batch[i];
#pragma unroll
        for (int q = 0; q < 4; q++) {
            float4 v = g_h2[i * 4 + q];
            h[4*q+0] = v.x; h[4*q+1] = v.y; h[4*q+2] = v.z; h[4*q+3] = v.w;
        }
    } else {
#pragma unroll
        for (int k = 0; k < HID; k++) h[k] = 0.0f;
    }
    int b0 = __shfl_sync(0xffffffffu, b, 0);
    bool uniform = __all_sync(0xffffffffu, b == b0);
    if (uniform && b0 >= 0) {
#pragma unroll
        for (int k = 0; k < HID; k++) {
#pragma unroll
            for (int off = 16; off > 0; off >>= 1)
                h[k] += __shfl_down_sync(0xffffffffu, h[k], off);
        }
        if (lane == 0) {
            float4* p = (float4*)&g_sums[b0 * HID];
#pragma unroll
            for (int q = 0; q < 4; q++)
                red4(p + q, h[4*q], h[4*q+1], h[4*q+2], h[4*q+3]);
            atomicAdd(&g_cnt[b0], 32.0f);
        }
    } else if (b >= 0) {
        float4* p = (float4*)&g_sums[b * HID];
#pragma unroll
        for (int q = 0; q < 4; q++)
            red4(p + q, h[4*q], h[4*q+1], h[4*q+2], h[4*q+3]);
        atomicAdd(&g_cnt[b], 1.0f);
    }
}

// out[g] = (sums[g]/max(cnt,1)) @ Wc + bc
__global__ __launch_bounds__(256) void k_final(const float* __restrict__ Wc,
                                               const float* __restrict__ bc,
                                               float* __restrict__ out) {
    int g = blockIdx.x * blockDim.x + threadIdx.x;
    if (g >= N_GRAPHS) return;
    float inv = 1.0f / fmaxf(g_cnt[g], 1.0f);
    float p[HID];
#pragma unroll
    for (int k = 0; k < HID; k++) p[k] = g_sums[g * HID + k] * inv;
#pragma unroll
    for (int j = 0; j < LABELS; j++) {
        float s = __ldg(&bc[j]);
#pragma unroll
        for (int k = 0; k < HID; k++) s = fmaf(p[k], __ldg(&Wc[k * LABELS + j]), s);
        out[g * LABELS + j] = s;
    }
}

// ---------------- launch -----------------------------------------------------
extern "C" void kernel_launch(void* const* d_in, const int* in_sizes, int n_in,
                              void* d_out, int out_size) {
    const int*   x    = (const int*)  d_in[0];
    const int*   ei   = (const int*)  d_in[1];
    const int*   batch= (const int*)  d_in[2];
    const float* emb  = (const float*)d_in[3];
    const float* W1   = (const float*)d_in[4];
    const float* b1   = (const float*)d_in[5];
    const float* W2   = (const float*)d_in[6];
    const float* b2   = (const float*)d_in[7];
    const float* Wc   = (const float*)d_in[8];
    const float* bc   = (const float*)d_in[9];
    float* out = (float*)d_out;

    int E = in_sizes[1] / 2;
    const int* src = ei;
    const int* dst = ei + E;

    int gn = (N_NODES + 255) / 256;
    int ge = (E + 255) / 256;
    int gw = (N_NODES * 32 + 255) / 256;   // warp per node

    k_init    <<<gn, 256>>>();
    k_deg     <<<ge, 256>>>(dst, E);
    k_scan1   <<<SCAN_NB, SCAN_BLK>>>();
    k_scan2   <<<1, 128>>>();
    k_scan3   <<<gn, 256>>>();
    k_scatter <<<ge, 256>>>(src, dst, E);
    k_ew      <<<1, 128>>>(emb, W1);
    k_a1      <<<gn, 256>>>(x);
    k_gather1 <<<gw, 256>>>(b1);
    k_l2      <<<gn, 256>>>(W2);
    k_gather2 <<<gw, 256>>>(b2);
    k_pool    <<<gn, 256>>>(batch);
    k_final   <<<(N_GRAPHS + 255) / 256, 256>>>(Wc, bc, out);
}